// round 11
// baseline (speedup 1.0000x reference)
#include <cuda_runtime.h>

// ---------------------------------------------------------------------------
// Problem constants
// ---------------------------------------------------------------------------
#define S0    2048
#define S1    256
#define SEQ   2304          // S0 + S1
#define DIM   1536          // model dim == H*D (coincidentally equal)
#define NH    24
#define HD    64
#define QKV_N 4608          // 3 * NH * HD

// ---------------------------------------------------------------------------
// Scratch (single static device buffer, ~99 MB)
// ---------------------------------------------------------------------------
// qkv0: 2048*4608 = 9,437,184
// qkv1:  256*4608 = 1,179,648
// Q/K/V: 24*2304*64 = 3,538,944 each
// O:     2304*1536 = 3,538,944
#define OFF_QKV0 0u
#define OFF_QKV1 9437184u
#define OFF_Q    10616832u
#define OFF_K    14155776u
#define OFF_V    17694720u
#define OFF_O    21233664u
#define SCRATCH_FLOATS 24772608u

__device__ float g_scratch[SCRATCH_FLOATS];

// ---------------------------------------------------------------------------
// SGEMM: C[M,N] = A[M,K] @ B[K,N], row-major, fp32.
// BM=BN=128, BK=8, 256 threads, 8x8 microtile. Requires M%128==0, N%128==0,
// K%8==0 (true for every GEMM in this problem).
// ---------------------------------------------------------------------------
__global__ void __launch_bounds__(256) sgemm128(
    const float* __restrict__ A, const float* __restrict__ B,
    float* __restrict__ C, int N, int K)
{
    __shared__ float As[8][128];   // transposed A tile
    __shared__ float Bs[8][128];

    const int tid = threadIdx.x;
    const int tx = tid & 15;       // 0..15 -> col block of 8
    const int ty = tid >> 4;       // 0..15 -> row block of 8

    const float* Ab = A + (size_t)blockIdx.y * 128 * K;
    const float* Bb = B + (size_t)blockIdx.x * 128;

    const int aRow = tid >> 1;          // 0..127
    const int aCol = (tid & 1) * 4;     // 0 or 4
    const int bRow = tid >> 5;          // 0..7
    const int bCol = (tid & 31) * 4;    // 0..124

    float acc[8][8];
    #pragma unroll
    for (int i = 0; i < 8; i++)
        #pragma unroll
        for (int j = 0; j < 8; j++) acc[i][j] = 0.f;

    for (int k0 = 0; k0 < K; k0 += 8) {
        float4 av = *(const float4*)(Ab + (size_t)aRow * K + k0 + aCol);
        As[aCol + 0][aRow] = av.x;
        As[aCol + 1][aRow] = av.y;
        As[aCol + 2][aRow] = av.z;
        As[aCol + 3][aRow] = av.w;
        float4 bv = *(const float4*)(Bb + (size_t)(k0 + bRow) * N + bCol);
        *(float4*)(&Bs[bRow][bCol]) = bv;
        __syncthreads();

        #pragma unroll
        for (int k = 0; k < 8; k++) {
            float ar[8], br[8];
            #pragma unroll
            for (int i = 0; i < 8; i++) ar[i] = As[k][ty * 8 + i];
            #pragma unroll
            for (int j = 0; j < 8; j++) br[j] = Bs[k][tx * 8 + j];
            #pragma unroll
            for (int i = 0; i < 8; i++)
                #pragma unroll
                for (int j = 0; j < 8; j++)
                    acc[i][j] = fmaf(ar[i], br[j], acc[i][j]);
        }
        __syncthreads();
    }

    #pragma unroll
    for (int i = 0; i < 8; i++) {
        float* Crow = C + (size_t)(blockIdx.y * 128 + ty * 8 + i) * N
                        + blockIdx.x * 128 + tx * 8;
        *(float4*)(Crow)     = make_float4(acc[i][0], acc[i][1], acc[i][2], acc[i][3]);
        *(float4*)(Crow + 4) = make_float4(acc[i][4], acc[i][5], acc[i][6], acc[i][7]);
    }
}

// ---------------------------------------------------------------------------
// RMSNorm + RoPE + scatter to (H, SEQ, HD) Q/K/V.
// One warp per (s_global, head). Thread d handles elements d and d+32 (the
// natural rotate-half pairing). RoPE position restarts per modality.
// ---------------------------------------------------------------------------
__global__ void norm_rope_kernel(
    const float* __restrict__ gq0, const float* __restrict__ gk0,
    const float* __restrict__ gq1, const float* __restrict__ gk1)
{
    const int s = blockIdx.x;
    const int h = blockIdx.y;
    const int d = threadIdx.x;     // 0..31

    const float* src;
    const float *gq, *gk;
    int pos;
    if (s < S0) {
        pos = s;
        src = g_scratch + OFF_QKV0 + (size_t)s * QKV_N;
        gq = gq0; gk = gk0;
    } else {
        pos = s - S0;
        src = g_scratch + OFF_QKV1 + (size_t)pos * QKV_N;
        gq = gq1; gk = gk1;
    }

    const int col = h * HD + d;    // within one qkv-slab of width H*D = 1536
    float qa = src[col],            qb = src[col + 32];
    float ka = src[DIM + col],      kb = src[DIM + col + 32];
    float va = src[2 * DIM + col],  vb = src[2 * DIM + col + 32];

    // RMSNorm over the 64 head-dim elements
    float ssq = qa * qa + qb * qb;
    float ssk = ka * ka + kb * kb;
    #pragma unroll
    for (int o = 16; o; o >>= 1) {
        ssq += __shfl_xor_sync(0xffffffffu, ssq, o);
        ssk += __shfl_xor_sync(0xffffffffu, ssk, o);
    }
    float rq = rsqrtf(ssq * (1.f / 64.f) + 1e-6f);
    float rk = rsqrtf(ssk * (1.f / 64.f) + 1e-6f);
    qa *= rq * gq[d]; qb *= rq * gq[d + 32];
    ka *= rk * gk[d]; kb *= rk * gk[d + 32];

    // RoPE: inv = 10000^(-(2d)/64); rotate-half
    float inv = powf(10000.f, -(float)(2 * d) * (1.f / 64.f));
    float f = (float)pos * inv;
    float sn, cs;
    sincosf(f, &sn, &cs);
    float qoa = qa * cs - qb * sn, qob = qb * cs + qa * sn;
    float koa = ka * cs - kb * sn, kob = kb * cs + ka * sn;

    const size_t base = ((size_t)h * SEQ + s) * HD;
    g_scratch[OFF_Q + base + d]      = qoa;
    g_scratch[OFF_Q + base + d + 32] = qob;
    g_scratch[OFF_K + base + d]      = koa;
    g_scratch[OFF_K + base + d + 32] = kob;
    g_scratch[OFF_V + base + d]      = va;
    g_scratch[OFF_V + base + d + 32] = vb;
}

// ---------------------------------------------------------------------------
// Flash attention. Block = (q-tile of 64 rows, head). 64 threads; thread t
// owns q-row t: q[64] and o[64] live in registers. K/V tiles (64x64 fp32) are
// staged in smem (reads are warp-broadcast float4 -> conflict-free). The
// score tile is stored transposed Ss[j][t] so both write (fixed j, t = lane)
// and read patterns are consecutive -> conflict-free. Online softmax.
// Output written as O[s][h*64+d] (matches reference transpose/reshape).
// ---------------------------------------------------------------------------
__global__ void __launch_bounds__(64) flash_kernel()
{
    __shared__ float Ks[64 * 64];
    __shared__ float Vs[64 * 64];
    __shared__ float Ss[64 * 64];

    const int qt = blockIdx.x;
    const int h  = blockIdx.y;
    const int t  = threadIdx.x;

    const float* Q = g_scratch + OFF_Q;
    const float* K = g_scratch + OFF_K;
    const float* V = g_scratch + OFF_V;

    // Load q row, pre-scaled by 1/sqrt(D) = 0.125
    float q[64];
    {
        const float* qp = Q + ((size_t)h * SEQ + qt * 64 + t) * HD;
        #pragma unroll
        for (int i = 0; i < 64; i += 4) {
            float4 v4 = *(const float4*)(qp + i);
            q[i]     = v4.x * 0.125f;
            q[i + 1] = v4.y * 0.125f;
            q[i + 2] = v4.z * 0.125f;
            q[i + 3] = v4.w * 0.125f;
        }
    }

    float o[64];
    #pragma unroll
    for (int i = 0; i < 64; i++) o[i] = 0.f;
    float m = -1e30f, l = 0.f;

    for (int kt = 0; kt < SEQ; kt += 64) {
        // Cooperative K/V tile load (coalesced float4)
        const float4* Kb = (const float4*)(K + ((size_t)h * SEQ + kt) * HD);
        const float4* Vb = (const float4*)(V + ((size_t)h * SEQ + kt) * HD);
        #pragma unroll
        for (int r = 0; r < 16; r++) {
            ((float4*)Ks)[r * 64 + t] = Kb[r * 64 + t];
            ((float4*)Vs)[r * 64 + t] = Vb[r * 64 + t];
        }
        __syncthreads();

        // s_j = q . k_j   (4 partial accumulators to break the FMA chain)
        float mt = m;
        for (int j = 0; j < 64; j++) {
            const float4* kr = (const float4*)(Ks + j * 64);
            float s0 = 0.f, s1 = 0.f, s2 = 0.f, s3 = 0.f;
            #pragma unroll
            for (int i = 0; i < 16; i++) {
                float4 kv = kr[i];
                s0 = fmaf(q[4 * i],     kv.x, s0);
                s1 = fmaf(q[4 * i + 1], kv.y, s1);
                s2 = fmaf(q[4 * i + 2], kv.z, s2);
                s3 = fmaf(q[4 * i + 3], kv.w, s3);
            }
            float s = (s0 + s1) + (s2 + s3);
            Ss[j * 64 + t] = s;
            mt = fmaxf(mt, s);
        }

        // Online softmax rescale
        float alpha = __expf(m - mt);
        m = mt;
        l *= alpha;
        #pragma unroll
        for (int i = 0; i < 64; i++) o[i] *= alpha;

        // o += p_j * v_j
        for (int j = 0; j < 64; j++) {
            float p = __expf(Ss[j * 64 + t] - m);
            l += p;
            const float4* vr = (const float4*)(Vs + j * 64);
            #pragma unroll
            for (int i = 0; i < 16; i++) {
                float4 vv = vr[i];
                o[4 * i]     = fmaf(p, vv.x, o[4 * i]);
                o[4 * i + 1] = fmaf(p, vv.y, o[4 * i + 1]);
                o[4 * i + 2] = fmaf(p, vv.z, o[4 * i + 2]);
                o[4 * i + 3] = fmaf(p, vv.w, o[4 * i + 3]);
            }
        }
        __syncthreads();
    }

    const float li = 1.f / l;
    float* op = g_scratch + OFF_O + (size_t)(qt * 64 + t) * DIM + h * HD;
    #pragma unroll
    for (int i = 0; i < 64; i += 4)
        *(float4*)(op + i) = make_float4(o[i] * li, o[i + 1] * li,
                                         o[i + 2] * li, o[i + 3] * li);
}

// ---------------------------------------------------------------------------
// Launch
// ---------------------------------------------------------------------------
extern "C" void kernel_launch(void* const* d_in, const int* in_sizes, int n_in,
                              void* d_out, int out_size)
{
    const float* x0     = (const float*)d_in[0];
    const float* x1     = (const float*)d_in[1];
    const float* w_qkv0 = (const float*)d_in[2];
    const float* w_qkv1 = (const float*)d_in[3];
    const float* w_out0 = (const float*)d_in[4];
    const float* w_out1 = (const float*)d_in[5];
    const float* gq0    = (const float*)d_in[6];
    const float* gk0    = (const float*)d_in[7];
    const float* gq1    = (const float*)d_in[8];
    const float* gk1    = (const float*)d_in[9];
    float* out = (float*)d_out;

    float* scratch = nullptr;
    cudaGetSymbolAddress((void**)&scratch, g_scratch);

    // 1) QKV projections
    sgemm128<<<dim3(QKV_N / 128, S0 / 128), 256>>>(x0, w_qkv0, scratch + OFF_QKV0, QKV_N, DIM);
    sgemm128<<<dim3(QKV_N / 128, S1 / 128), 256>>>(x1, w_qkv1, scratch + OFF_QKV1, QKV_N, DIM);

    // 2) RMSNorm + RoPE + scatter to (H, SEQ, HD)
    norm_rope_kernel<<<dim3(SEQ, NH), 32>>>(gq0, gk0, gq1, gk1);

    // 3) Flash attention -> O[SEQ, H*D]
    flash_kernel<<<dim3(SEQ / 64, NH), 64>>>();

    // 4) Output projections (o0 then o1, contiguous in d_out)
    sgemm128<<<dim3(DIM / 128, S0 / 128), 256>>>(scratch + OFF_O, w_out0, out, DIM, DIM);
    sgemm128<<<dim3(DIM / 128, S1 / 128), 256>>>(scratch + OFF_O + (size_t)S0 * DIM,
                                                 w_out1, out + (size_t)S0 * DIM, DIM, DIM);
}